// round 11
// baseline (speedup 1.0000x reference)
#include <cuda_runtime.h>
#include <cstdint>

// Problem constants
#define T_DIM 8
#define C_DIM 4
#define NMAPS (T_DIM * C_DIM)        // 32
#define H_DIM 1024
#define W_DIM 1024
#define NUM_GRID 16
#define NCELLS (NUM_GRID * NUM_GRID) // 256
#define THRESH 0.65f
#define NUM_FG 40
#define NUM_BG 1
#define MAX_PTS 42

#define BLOCKS_PER_MAP 16            // one block per grid-row (16 cells, 64 rows)
#define NSTAGES 3
#define RPS 4                        // rows per stage (4 contiguous rows = 16KB)
#define STAGE_F4 (RPS * 256)         // 1024 float4
#define STAGE_BYTES (STAGE_F4 * 16)  // 16384
#define NST_TOT 16                   // 64 rows / RPS
#define SBUF_BYTES (NSTAGES * STAGE_BYTES)   // 49152
#define DYN_SMEM (SBUF_BYTES + 64)           // + mbarriers

// Scratch (__device__ globals; no allocations allowed)
__device__ unsigned long long g_cellpack[NMAPS * NCELLS];
__device__ unsigned long long g_blockmin[NMAPS * BLOCKS_PER_MAP];
__device__ int g_ctr[NMAPS];         // self-resetting -> graph-replay safe

__device__ __forceinline__ uint32_t cvta_smem(const void* p) {
    return (uint32_t)__cvta_generic_to_shared(p);
}
__device__ __forceinline__ void mbar_init(uint32_t a, uint32_t c) {
    asm volatile("mbarrier.init.shared.b64 [%0], %1;" :: "r"(a), "r"(c) : "memory");
}
__device__ __forceinline__ void mbar_expect(uint32_t a, uint32_t bytes) {
    asm volatile("mbarrier.arrive.expect_tx.shared.b64 _, [%0], %1;"
                 :: "r"(a), "r"(bytes) : "memory");
}
__device__ __forceinline__ void mbar_wait(uint32_t a, uint32_t parity) {
    asm volatile("{\n\t"
        ".reg .pred P;\n\t"
        "LAB_%=:\n\t"
        "mbarrier.try_wait.parity.shared.b64 P, [%0], %1;\n\t"
        "@P bra DONE_%=;\n\t"
        "bra LAB_%=;\n\t"
        "DONE_%=:\n\t"
        "}" :: "r"(a), "r"(parity) : "memory");
}
__device__ __forceinline__ void bulk_g2s(uint32_t dst, const void* src,
                                         uint32_t bytes, uint32_t mbar) {
    asm volatile(
        "cp.async.bulk.shared::cluster.global.mbarrier::complete_tx::bytes "
        "[%0], [%1], %2, [%3];"
        :: "r"(dst), "l"(src), "r"(bytes), "r"(mbar) : "memory");
}
__device__ __forceinline__ void fence_proxy_async_cta() {
    asm volatile("fence.proxy.async.shared::cta;" ::: "memory");
}

// ---------------------------------------------------------------------------
// Fused kernel. Block = 256 threads = one grid-row of one map (64 rows x
// 1024 cols = 16 cells). TMA bulk 3-stage ring feeds SMEM; thread t owns
// columns 4t..4t+3 for every row. Last block per map runs selection.
// ---------------------------------------------------------------------------
__global__ __launch_bounds__(256) void k_fused(const float* __restrict__ sims,
                                               const int* __restrict__ osz,
                                               float* __restrict__ out,
                                               int write_nums, int nums_off) {
    extern __shared__ char smem_raw[];
    float4* sbuf = reinterpret_cast<float4*>(smem_raw);
    unsigned long long* mbar64 =
        reinterpret_cast<unsigned long long*>(smem_raw + SBUF_BYTES);

    const int b    = blockIdx.x;           // 0..511
    const int m    = b >> 4;               // map id
    const int gy   = b & 15;               // grid row within map
    const int tid  = threadIdx.x;
    const int warp = tid >> 5;
    const int lane = tid & 31;
    const int rowbase = gy << 6;           // first image row of this block

    const float* __restrict__ base = sims + (size_t)m * (H_DIM * W_DIM);
    const uint32_t sb0  = cvta_smem(&sbuf[0]);
    const uint32_t mb0  = cvta_smem(&mbar64[0]);

    // init barriers (fresh smem each launch -> graph-replay safe)
    if (tid == 0) {
        #pragma unroll
        for (int i = 0; i < NSTAGES; ++i) mbar_init(mb0 + 8u * i, 1);
        fence_proxy_async_cta();
    }
    __syncthreads();

    // prologue: issue stages 0..NSTAGES-2
    if (tid == 0) {
        #pragma unroll
        for (int st = 0; st < NSTAGES - 1; ++st) {
            const uint32_t bar = mb0 + 8u * st;
            mbar_expect(bar, STAGE_BYTES);
            bulk_g2s(sb0 + (uint32_t)st * STAGE_BYTES,
                     base + ((unsigned)(rowbase + st * RPS) << 10),
                     STAGE_BYTES, bar);
        }
    }

    float    minv = __int_as_float(0x7f800000);      // +inf
    float    maxv = -minv;
    unsigned maxi = 0u, mini = 0u;
    const unsigned colbase = (unsigned)tid << 2;

    for (int s = 0; s < NST_TOT; ++s) {
        const int bi = s % NSTAGES;
        mbar_wait(mb0 + 8u * bi, (uint32_t)((s / NSTAGES) & 1));

        // consume stage s: rows ascend; strict cmps keep EARLIEST index
        const int fb = bi * STAGE_F4;
        #pragma unroll
        for (int r = 0; r < RPS; ++r) {
            const float4 v = sbuf[fb + r * 256 + tid];
            const unsigned idx = ((unsigned)(rowbase + s * RPS + r) << 10) + colbase;

            float    m01 = fmaxf(v.x, v.y);
            unsigned i01 = (v.y > v.x) ? idx + 1 : idx;
            float    m23 = fmaxf(v.z, v.w);
            unsigned i23 = (v.w > v.z) ? idx + 3 : idx + 2;
            float    mq  = fmaxf(m01, m23);
            unsigned iq  = (m23 > m01) ? i23 : i01;
            if (mq > maxv) { maxv = mq; maxi = iq; }

            float    n01 = fminf(v.x, v.y);
            unsigned j01 = (v.y < v.x) ? idx + 1 : idx;
            float    n23 = fminf(v.z, v.w);
            unsigned j23 = (v.w < v.z) ? idx + 3 : idx + 2;
            float    nq  = fminf(n01, n23);
            unsigned jq  = (n23 < n01) ? j23 : j01;
            if (nq < minv) { minv = nq; mini = jq; }
        }
        __syncthreads();          // whole block done with buffer bi

        if (tid == 0 && s + NSTAGES - 1 < NST_TOT) {
            const int st = s + NSTAGES - 1;
            const int bj = st % NSTAGES;
            const uint32_t bar = mb0 + 8u * bj;
            mbar_expect(bar, STAGE_BYTES);
            bulk_g2s(sb0 + (uint32_t)bj * STAGE_BYTES,
                     base + ((unsigned)(rowbase + st * RPS) << 10),
                     STAGE_BYTES, bar);
        }
    }

    // ---- cell max: lexicographic reduce within each 16-lane group ----
    #pragma unroll
    for (int o = 8; o > 0; o >>= 1) {
        float    ov = __shfl_down_sync(0xffffffffu, maxv, o);
        unsigned oi = __shfl_down_sync(0xffffffffu, maxi, o);
        if (ov > maxv || (ov == maxv && oi < maxi)) { maxv = ov; maxi = oi; }
    }
    if ((lane & 15) == 0) {
        const int cid = (gy << 4) + (tid >> 4);          // cell id 0..255
        g_cellpack[m * NCELLS + cid] =
            ((unsigned long long)__float_as_uint(maxv) << 32) | (unsigned long long)maxi;
    }

    // ---- map min: full warp reduce, then block reduce ----
    #pragma unroll
    for (int o = 16; o > 0; o >>= 1) {
        float    nv = __shfl_down_sync(0xffffffffu, minv, o);
        unsigned ni = __shfl_down_sync(0xffffffffu, mini, o);
        if (nv < minv || (nv == minv && ni < mini)) { minv = nv; mini = ni; }
    }

    __shared__ unsigned long long sminkey[8];
    if (lane == 0) {
        // orderable transform (values are non-negative floats): bits ^ 0x80000000
        sminkey[warp] =
            ((unsigned long long)(__float_as_uint(minv) ^ 0x80000000u) << 32) |
            (unsigned long long)mini;
    }
    __syncthreads();

    __shared__ int s_last;
    if (tid == 0) {
        unsigned long long k = sminkey[0];
        #pragma unroll
        for (int j = 1; j < 8; ++j) k = min(k, sminkey[j]);
        g_blockmin[m * BLOCKS_PER_MAP + gy] = k;
        __threadfence();                          // publish cellpack + blockmin
        const int c = atomicAdd(&g_ctr[m], 1);
        s_last = (c == BLOCKS_PER_MAP - 1);
        if (s_last) g_ctr[m] = 0;                 // self-reset for graph replays
    }
    __syncthreads();
    if (!s_last) return;

    // ======================= selection phase (last block) ==================
    // alias selection arrays onto the (fully consumed) staging buffer
    float*    sval = reinterpret_cast<float*>(smem_raw);
    unsigned* sidx = reinterpret_cast<unsigned*>(smem_raw + 1024);
    __shared__ unsigned long long s_mink;

    const unsigned long long p = g_cellpack[m * NCELLS + tid];
    const float    v   = __uint_as_float((unsigned)(p >> 32));
    const unsigned idx = (unsigned)p;
    sval[tid] = v;
    sidx[tid] = idx;

    if (tid < 32) {                               // reduce the 16 block mins
        unsigned long long k = (tid < BLOCKS_PER_MAP)
            ? g_blockmin[m * BLOCKS_PER_MAP + tid] : ~0ULL;
        #pragma unroll
        for (int o = 8; o > 0; o >>= 1)
            k = min(k, __shfl_down_sync(0xffffffffu, k, o));
        if (tid == 0) s_mink = k;
    }

    float* __restrict__ orow = out + (size_t)m * (MAX_PTS * 4);
    if (tid < MAX_PTS) {
        reinterpret_cast<float4*>(orow)[tid] = make_float4(0.f, 0.f, 0.f, 0.f);
    }

    const bool valid   = (v > THRESH);
    const int  count   = __syncthreads_count(valid);   // barrier: sval/zero done
    const int  n_valid = count < NUM_FG ? count : NUM_FG;
    const bool any_fg  = (count > 0);

    const int   t  = m / C_DIM;
    const float sx = (float)osz[t * 2 + 1] / (float)W_DIM;
    const float sy = (float)osz[t * 2 + 0] / (float)H_DIM;

    // rank = #cells strictly better: (score desc, cell-id asc) == stable argsort
    const float NEGINF = -__int_as_float(0x7f800000);
    const float effv = valid ? v : NEGINF;
    int rank = 0;
    #pragma unroll 8
    for (int j = 0; j < NCELLS; ++j) {
        const float jv = sval[j];
        const float ej = (jv > THRESH) ? jv : NEGINF;
        rank += (int)((ej > effv) || (ej == effv && j < tid));
    }

    if (any_fg) {
        if (valid && rank < NUM_FG) {
            const float px = (float)(idx & (W_DIM - 1));
            const float py = (float)(idx >> 10);
            reinterpret_cast<float4*>(orow)[rank] =
                make_float4(px * sx, py * sy, v, 1.0f);
        }
    } else if (tid == 0) {
        // fallback: global argmax (value desc, idx asc) over cell maxima
        float    bv = sval[0];
        unsigned bi = sidx[0];
        for (int j = 1; j < NCELLS; ++j) {
            if (sval[j] > bv || (sval[j] == bv && sidx[j] < bi)) { bv = sval[j]; bi = sidx[j]; }
        }
        const float px = (float)(bi & (W_DIM - 1));
        const float py = (float)(bi >> 10);
        reinterpret_cast<float4*>(orow)[0] = make_float4(px * sx, py * sy, bv, 1.0f);
    }

    const int fg_count = any_fg ? n_valid : 1;
    if (tid == 0) {
        const unsigned long long k = s_mink;
        const float    bvv = __uint_as_float(((unsigned)(k >> 32)) ^ 0x80000000u);
        const unsigned bii = (unsigned)k;
        const float px = (float)(bii & (W_DIM - 1));
        const float py = (float)(bii >> 10);
        reinterpret_cast<float4*>(orow)[fg_count] =
            make_float4(px * sx, py * sy, bvv, 0.0f);
        if (write_nums)
            out[nums_off + m] = (float)(fg_count + NUM_BG);
    }
}

extern "C" void kernel_launch(void* const* d_in, const int* in_sizes, int n_in,
                              void* d_out, int out_size) {
    const float* sims = (const float*)d_in[0];
    // d_in[1] = category_ids (unused by the reference computation)
    const int* osz = (const int*)d_in[2];
    float* out = (float*)d_out;

    const int pts_elems = NMAPS * MAX_PTS * 4;                 // 5376
    const int write_nums = (out_size >= pts_elems + NMAPS) ? 1 : 0;

    cudaFuncSetAttribute(k_fused, cudaFuncAttributeMaxDynamicSharedMemorySize,
                         DYN_SMEM);
    k_fused<<<NMAPS * BLOCKS_PER_MAP, 256, DYN_SMEM>>>(
        sims, osz, out, write_nums, pts_elems);
}